// round 2
// baseline (speedup 1.0000x reference)
#include <cuda_runtime.h>

// ---------------- problem constants ----------------
#define BATCH    16384
#define INDIM    219      // 24*8 + 3 + 8 + 16
#define HID      64
#define NB       9        // 1 silu base + 8 spline bases
#define ROWS     32       // rows per block
#define CI       16       // input-chunk size
#define THREADS  256

// Packed layer-1 weights: W[i][g][o], g=0 -> w_base1, g=1..8 -> coef1[...,g-1]
__device__ __align__(16) float W_pack[INDIM * NB * HID];   // 504 KB, L2-resident

// ---------------- helpers ----------------
__device__ __forceinline__ float siluf(float x) {
    return x / (1.0f + __expf(-x));
}

__device__ __forceinline__ void ffma2(unsigned long long& acc,
                                      unsigned long long a,
                                      unsigned long long w) {
    asm("fma.rn.f32x2 %0, %1, %2, %0;" : "+l"(acc) : "l"(a), "l"(w));
}

// Uniform cubic B-spline local weights.
// Grid: knots k_j = -2.2 + 0.4*j, j=0..11; 8 cubic bases (j=0..7).
// For x in [k_m, k_{m+1}): active bases j = m-3..m with values n0..n3.
__device__ __forceinline__ void spline_local(float x, int& m,
                                             float& n0, float& n1,
                                             float& n2, float& n3) {
    float tt = (x + 2.2f) * 2.5f;
    float mf = floorf(tt);
    m = (int)mf;
    float u = tt - mf;
    float v = 1.0f - u;
    float u2 = u * u, u3 = u2 * u;
    n0 = v * v * v * (1.0f / 6.0f);
    n1 = (3.0f * u3 - 6.0f * u2 + 4.0f) * (1.0f / 6.0f);
    n2 = (-3.0f * u3 + 3.0f * u2 + 3.0f * u + 1.0f) * (1.0f / 6.0f);
    n3 = u3 * (1.0f / 6.0f);
}

// ---------------- weight repack ----------------
__global__ void repack_kernel(const float* __restrict__ wb1,
                              const float* __restrict__ c1) {
    int idx = blockIdx.x * blockDim.x + threadIdx.x;   // over 219*64
    if (idx < INDIM * HID) {
        int i = idx / HID;
        int o = idx - i * HID;
        W_pack[(i * NB + 0) * HID + o] = wb1[idx];
#pragma unroll
        for (int g = 0; g < 8; g++)
            W_pack[(i * NB + 1 + g) * HID + o] = c1[idx * 8 + g];
    }
}

// ---------------- fused KAN forward ----------------
__global__ __launch_bounds__(THREADS)
void kan_main(const float* __restrict__ hist,
              const float* __restrict__ statf,
              const float* __restrict__ timef,
              const int*   __restrict__ st_idx,
              const float* __restrict__ emb,
              const float* __restrict__ wb2,
              const float* __restrict__ c2,
              float* __restrict__ out) {
    // Activation tile, duplicated for f32x2: a2[row][i_local*9 + g] = {a, a}
    __shared__ float2 a2[ROWS][CI * NB];      // 36,864 B
    __shared__ int sidx[ROWS];

    const int t = threadIdx.x;
    const int row0 = blockIdx.x * ROWS;
    if (t < ROWS) sidx[t] = st_idx[row0 + t];
    __syncthreads();

    const int o4 = t & 15;      // output quad: owns outputs o4*4 .. o4*4+3
    const int rg = t >> 4;      // row group: owns rows rg*2, rg*2+1

    unsigned long long acc00 = 0ull, acc01 = 0ull, acc10 = 0ull, acc11 = 0ull;

    for (int i0 = 0; i0 < INDIM; i0 += CI) {
        const int ci = min(CI, INDIM - i0);

        // ---- phase A: build activations for this chunk ----
        for (int it = t; it < ROWS * ci; it += THREADS) {
            int row = it / ci;
            int il  = it - row * ci;
            int i   = i0 + il;
            int rb  = row0 + row;
            float x;
            if (i < 192)      x = hist[rb * 192 + i];
            else if (i < 195) x = statf[rb * 3 + (i - 192)];
            else if (i < 203) x = timef[rb * 8 + (i - 195)];
            else              x = emb[sidx[row] * 16 + (i - 203)];

            float2* dst = &a2[row][il * NB];
            float s = siluf(x);
            dst[0] = make_float2(s, s);
#pragma unroll
            for (int g = 1; g < NB; g++) dst[g] = make_float2(0.0f, 0.0f);

            int m; float n0, n1, n2, n3;
            spline_local(x, m, n0, n1, n2, n3);
            if (m >= 0 && m <= 10) {
                int j0 = m - 3;
                if (m >= 3)           dst[1 + j0]     = make_float2(n0, n0);
                if (m >= 2 && m <= 9) dst[1 + j0 + 1] = make_float2(n1, n1);
                if (m >= 1 && m <= 8) dst[1 + j0 + 2] = make_float2(n2, n2);
                if (m <= 7)           dst[1 + m]      = make_float2(n3, n3);
            }
        }
        __syncthreads();

        // ---- phase B: accumulate GEMM slice via packed f32x2 FMA ----
        const ulonglong2* wrow =
            reinterpret_cast<const ulonglong2*>(W_pack + (size_t)i0 * NB * HID) + o4;
        const unsigned long long* arow0 =
            reinterpret_cast<const unsigned long long*>(&a2[rg * 2 + 0][0]);
        const unsigned long long* arow1 =
            reinterpret_cast<const unsigned long long*>(&a2[rg * 2 + 1][0]);
        const int rmax = ci * NB;
#pragma unroll 9
        for (int r = 0; r < rmax; r++) {
            ulonglong2 w = wrow[(size_t)r * 16];   // 64-float row stride = 16 u2
            unsigned long long a0 = arow0[r];
            unsigned long long a1 = arow1[r];
            ffma2(acc00, a0, w.x);
            ffma2(acc01, a0, w.y);
            ffma2(acc10, a1, w.x);
            ffma2(acc11, a1, w.y);
        }
        __syncthreads();
    }

    // ---- hand off h = layer-1 output through shared (reuse a2 buffer) ----
    float* h = reinterpret_cast<float*>(a2);   // [ROWS][64]
    *reinterpret_cast<float2*>(&h[(rg * 2 + 0) * HID + o4 * 4])     = *reinterpret_cast<float2*>(&acc00);
    *reinterpret_cast<float2*>(&h[(rg * 2 + 0) * HID + o4 * 4 + 2]) = *reinterpret_cast<float2*>(&acc01);
    *reinterpret_cast<float2*>(&h[(rg * 2 + 1) * HID + o4 * 4])     = *reinterpret_cast<float2*>(&acc10);
    *reinterpret_cast<float2*>(&h[(rg * 2 + 1) * HID + o4 * 4 + 2]) = *reinterpret_cast<float2*>(&acc11);
    __syncthreads();

    // ---- layer 2: 8 threads per row, each covers 8 hidden units ----
    const int row = t >> 3;
    const int sub = t & 7;
    float acc = 0.0f;
#pragma unroll
    for (int k = 0; k < 8; k++) {
        int o = sub + k * 8;
        float xv = h[row * HID + o];
        float v = siluf(xv) * __ldg(&wb2[o]);

        int m; float n0, n1, n2, n3;
        spline_local(xv, m, n0, n1, n2, n3);
        if (m >= 0 && m <= 10) {
            int j0 = m - 3;
#pragma unroll
            for (int j = 0; j < 8; j++) {
                int d = j - j0;
                float nb = (d == 0) ? n0 : (d == 1) ? n1 : (d == 2) ? n2
                         : (d == 3) ? n3 : 0.0f;
                v += nb * __ldg(&c2[o * 8 + j]);
            }
        }
        acc += v;
    }
    acc += __shfl_xor_sync(0xffffffffu, acc, 4);
    acc += __shfl_xor_sync(0xffffffffu, acc, 2);
    acc += __shfl_xor_sync(0xffffffffu, acc, 1);
    if (sub == 0) out[row0 + row] = acc;
}

// ---------------- launch ----------------
extern "C" void kernel_launch(void* const* d_in, const int* in_sizes, int n_in,
                              void* d_out, int out_size) {
    const float* hist  = (const float*)d_in[0];
    const float* statf = (const float*)d_in[1];
    const float* timef = (const float*)d_in[2];
    const int*   sti   = (const int*)  d_in[3];
    const float* emb   = (const float*)d_in[4];
    const float* wb1   = (const float*)d_in[5];
    const float* c1    = (const float*)d_in[6];
    const float* wb2   = (const float*)d_in[7];
    const float* c2    = (const float*)d_in[8];
    float* out = (float*)d_out;

    repack_kernel<<<(INDIM * HID + 255) / 256, 256>>>(wb1, c1);
    kan_main<<<BATCH / ROWS, THREADS>>>(hist, statf, timef, sti, emb, wb2, c2, out);
}